// round 12
// baseline (speedup 1.0000x reference)
#include <cuda_runtime.h>

#define NB 32
#define TT 16384
#define HH 64
#define GG 384         // 12 warps: 4 gate, 4 z-producer, 4 n-producer
#define XCHUNK 64      // x prefetch chunk

typedef unsigned long long ull;

// ---- packed f32x2 helpers ----
__device__ __forceinline__ ull fma2(ull a, ull b, ull c) {
    ull d;
    asm("fma.rn.f32x2 %0, %1, %2, %3;" : "=l"(d) : "l"(a), "l"(b), "l"(c));
    return d;
}
__device__ __forceinline__ ull add2(ull a, ull b) {
    ull d;
    asm("add.rn.f32x2 %0, %1, %2;" : "=l"(d) : "l"(a), "l"(b));
    return d;
}
__device__ __forceinline__ void unpack2(ull v, float& lo, float& hi) {
    asm("mov.b64 {%0, %1}, %2;" : "=f"(lo), "=f"(hi) : "l"(v));
}
__device__ __forceinline__ ull pack2(float lo, float hi) {
    ull v;
    asm("mov.b64 %0, {%1, %2};" : "=l"(v) : "f"(lo), "f"(hi));
    return v;
}

// MUFU.TANH gates — validated rel_err ~2e-6 over the full recurrence
__device__ __forceinline__ float tanh_a(float v) {
    float r;
    asm("tanh.approx.f32 %0, %1;" : "=f"(r) : "f"(v));
    return r;
}
__device__ __forceinline__ float sig_a(float v) {
    return fmaf(0.5f, tanh_a(0.5f * v), 0.5f);
}

#define NBAR_SYNC(id, cnt) \
    asm volatile("bar.sync %0, %1;" :: "r"(id), "r"(cnt) : "memory")
#define NBAR_ARRIVE(id, cnt) \
    asm volatile("bar.arrive %0, %1;" :: "r"(id), "r"(cnt) : "memory")

// 32-col half-dot: 16 fma2 over register-resident half-row, 4 accumulators.
__device__ __forceinline__ float dot_half(const ull* w, const float* h_half,
                                          float bias) {
    const ulonglong2* hp = (const ulonglong2*)h_half;
    ull a0 = pack2(bias, 0.0f), a1 = 0ull, a2 = 0ull, a3 = 0ull;
    #pragma unroll
    for (int j = 0; j < 4; j++) {
        ulonglong2 v0 = hp[2 * j];
        ulonglong2 v1 = hp[2 * j + 1];
        a0 = fma2(w[4 * j],     v0.x, a0);
        a1 = fma2(w[4 * j + 1], v0.y, a1);
        a2 = fma2(w[4 * j + 2], v1.x, a2);
        a3 = fma2(w[4 * j + 3], v1.y, a3);
    }
    float lo, hi;
    unpack2(add2(add2(a0, a1), add2(a2, a3)), lo, hi);
    return lo + hi;
}

// ---------------------------------------------------------------------------
// Balanced warp-specialized scan. One block per batch, 384 threads.
// Lane pair (even,odd) owns one W_hh row: even = cols 0-31, odd = cols 32-63;
// halves combine with one shfl.bfly(1). 12 warps -> 3/SMSP, FMA pipes evenly
// loaded (192-cyc floor vs 256 unbalanced in the 192-thread version).
//   threads [0,128):   gate rows 0-63   — r-dot + r-sigmoid local; tail.
//   threads [128,256): z rows 64-127    — publish sigma(xpz + gh_z).
//   threads [256,384): n rows 128-191   — publish gh_n; odd lanes shadow-store
//                      states[t-1] from h_sh at the start of step t.
// Barriers: bar1 (zn ready: producers arrive, gates sync, count 384)
//           bar3 (h ready: full sync by all 384)
// ---------------------------------------------------------------------------
__global__ void __launch_bounds__(GG, 1) gru_scan_kernel(
    const float* __restrict__ x,
    const float* __restrict__ W_ih,
    const float* __restrict__ W_hh,
    const float* __restrict__ b_ih,
    const float* __restrict__ b_hh,
    float* __restrict__ states)
{
    const int b = blockIdx.x;
    const int t_id = threadIdx.x;
    const int role = t_id >> 7;          // 0 gate, 1 z, 2 n
    const int rloc = (t_id & 127) >> 1;  // local row 0..63
    const int half = t_id & 1;           // 0: cols 0-31, 1: cols 32-63
    const int colbase = half << 5;
    const int grow = role * HH + rloc;   // W_hh row

    __shared__ float h_sh[HH];
    __shared__ float2 zn_sh[HH];         // .x = sigma(z-pre), .y = gh_n
    __shared__ float x_sh[2][XCHUNK];

    // Register-resident half-row of W_hh (128B).
    ull w[16];
    {
        const ulonglong2* wr = (const ulonglong2*)(W_hh + (size_t)grow * HH + colbase);
        #pragma unroll
        for (int j = 0; j < 8; j++) {
            ulonglong2 v = wr[j];
            w[2 * j]     = v.x;
            w[2 * j + 1] = v.y;
        }
    }
    const float bhh = half ? 0.0f : b_hh[grow];   // bias counted once per row

    const float* xb = x + (size_t)b * TT;
    float* st_base = states + (size_t)b * TT * HH;

    if (t_id < HH) {
        h_sh[t_id] = 0.0f;
        x_sh[0][t_id] = xb[t_id];
    }
    __syncthreads();

    if (role == 0) {
        // ---------------- gate threads (rows 0-63) ----------------
        const float wir = W_ih[rloc],          bir = b_ih[rloc];
        const float win = W_ih[2 * HH + rloc], bin = b_ih[2 * HH + rloc];
        float h = 0.0f, xnext = 0.0f;
        int tmod = 0, buf = 0;

        for (int t = 0; t < TT; t++) {
            // x double-buffer (even lanes): LDG at chunk start, commit mid-chunk
            if (half == 0) {
                if (tmod == 0) {
                    int tn = t + XCHUNK;
                    if (tn < TT) xnext = xb[tn + rloc];
                } else if (tmod == XCHUNK / 2) {
                    if (t + XCHUNK / 2 < TT) x_sh[buf ^ 1][rloc] = xnext;
                }
            }

            float d = dot_half(w, h_sh + colbase, bhh);
            d += __shfl_xor_sync(0xffffffffu, d, 1);

            float r = 0.0f, xpn = 0.0f;
            if (half == 0) {
                const float xt = x_sh[buf][tmod];
                r   = sig_a(fmaf(xt, wir, bir) + d);
                xpn = fmaf(xt, win, bin);
            }

            NBAR_SYNC(1, GG);                    // wait z/n publishes
            if (half == 0) {
                const float2 zn = zn_sh[rloc];   // one LDS.64
                const float n = tanh_a(fmaf(r, zn.y, xpn));
                h = n + zn.x * (h - n);          // (1-z)*n + z*h
                h_sh[rloc] = h;
            }
            NBAR_SYNC(3, GG);                    // h visible to all

            if (++tmod == XCHUNK) { tmod = 0; buf ^= 1; }
        }
    } else if (role == 1) {
        // ---------------- z producers (rows 64-127) ----------------
        const float wiz = W_ih[HH + rloc], biz = b_ih[HH + rloc];
        int tmod = 0, buf = 0;
        for (int t = 0; t < TT; t++) {
            float d = dot_half(w, h_sh + colbase, bhh);
            d += __shfl_xor_sync(0xffffffffu, d, 1);
            if (half == 0) {
                const float xt = x_sh[buf][tmod];
                zn_sh[rloc].x = sig_a(fmaf(xt, wiz, biz) + d);
            }
            NBAR_ARRIVE(1, GG);
            NBAR_SYNC(3, GG);
            if (++tmod == XCHUNK) { tmod = 0; buf ^= 1; }
        }
    } else {
        // ---------------- n producers (rows 128-191) ----------------
        for (int t = 0; t < TT; t++) {
            // odd lanes: shadow-store states[t-1] (h_sh still holds h(t-1)
            // until gates pass bar1, which requires our bar1 arrive below)
            float hprev = 0.0f;
            if (half == 1 && t > 0) hprev = h_sh[rloc];

            float d = dot_half(w, h_sh + colbase, bhh);
            d += __shfl_xor_sync(0xffffffffu, d, 1);
            if (half == 0) {
                zn_sh[rloc].y = d;
            } else if (t > 0) {
                st_base[(size_t)(t - 1) * HH + rloc] = hprev;
            }
            NBAR_ARRIVE(1, GG);
            NBAR_SYNC(3, GG);
        }
        // final state (h_sh holds h(TT-1) after last bar3)
        if (half == 1)
            st_base[(size_t)(TT - 1) * HH + rloc] = h_sh[rloc];
    }
}

// ---------------------------------------------------------------------------
// Head: out[b,t] = states[b,t,:].W_out + b_out + x[b,t]. One warp per (b,t).
// ---------------------------------------------------------------------------
__global__ void head_kernel(const float* __restrict__ states,
                            const float* __restrict__ x,
                            const float* __restrict__ W_out,
                            const float* __restrict__ b_out,
                            float* __restrict__ out)
{
    const int lane = threadIdx.x & 31;
    const int warp = (int)((blockIdx.x * blockDim.x + threadIdx.x) >> 5);
    const int nw = (int)((gridDim.x * blockDim.x) >> 5);
    const float w0 = W_out[lane];
    const float w1 = W_out[32 + lane];
    const float bo = b_out[0];
    const long total = (long)NB * TT;
    for (long i = warp; i < total; i += nw) {
        const float* s = states + (size_t)i * HH;
        float p = fmaf(s[lane], w0, s[lane + 32] * w1);
        #pragma unroll
        for (int o = 16; o > 0; o >>= 1)
            p += __shfl_xor_sync(0xffffffffu, p, o);
        if (lane == 0) out[i] = p + bo + x[i];
    }
}

extern "C" void kernel_launch(void* const* d_in, const int* in_sizes, int n_in,
                              void* d_out, int out_size) {
    const float* x     = (const float*)d_in[0];
    const float* W_ih  = (const float*)d_in[1];
    const float* W_hh  = (const float*)d_in[2];
    const float* b_ih  = (const float*)d_in[3];
    const float* b_hh  = (const float*)d_in[4];
    const float* W_out = (const float*)d_in[5];
    const float* b_out = (const float*)d_in[6];

    float* out    = (float*)d_out;              // [B*T]   (tuple elem 0)
    float* states = out + (size_t)NB * TT;      // [B*T*H] (tuple elem 1)

    gru_scan_kernel<<<NB, GG>>>(x, W_ih, W_hh, b_ih, b_hh, states);
    head_kernel<<<512, 256>>>(states, x, W_out, b_out, out);
}

// round 15
// speedup vs baseline: 3.1849x; 3.1849x over previous
#include <cuda_runtime.h>

#define NB 32
#define TT 16384
#define HH 64
#define BT 128         // 4 warps: 2 gate, 2 producer
#define XCHUNK 64      // x prefetch chunk

typedef unsigned long long ull;

// ---- packed f32x2 helpers ----
__device__ __forceinline__ ull fma2(ull a, ull b, ull c) {
    ull d;
    asm("fma.rn.f32x2 %0, %1, %2, %3;" : "=l"(d) : "l"(a), "l"(b), "l"(c));
    return d;
}
__device__ __forceinline__ ull add2(ull a, ull b) {
    ull d;
    asm("add.rn.f32x2 %0, %1, %2;" : "=l"(d) : "l"(a), "l"(b));
    return d;
}
__device__ __forceinline__ void unpack2(ull v, float& lo, float& hi) {
    asm("mov.b64 {%0, %1}, %2;" : "=f"(lo), "=f"(hi) : "l"(v));
}
__device__ __forceinline__ ull pack2(float lo, float hi) {
    ull v;
    asm("mov.b64 %0, {%1, %2};" : "=l"(v) : "f"(lo), "f"(hi));
    return v;
}

// MUFU.TANH gates — validated rel_err ~2e-6 over the full recurrence
__device__ __forceinline__ float tanh_a(float v) {
    float r;
    asm("tanh.approx.f32 %0, %1;" : "=f"(r) : "f"(v));
    return r;
}
__device__ __forceinline__ float sig_a(float v) {
    return fmaf(0.5f, tanh_a(0.5f * v), 0.5f);
}

#define NBAR_SYNC(id, cnt) \
    asm volatile("bar.sync %0, %1;" :: "r"(id), "r"(cnt) : "memory")
#define NBAR_ARRIVE(id, cnt) \
    asm volatile("bar.arrive %0, %1;" :: "r"(id), "r"(cnt) : "memory")

// load a 64-float (32-ull) row slice into registers via 16B vectors
__device__ __forceinline__ void load_row32(ull* dst, const float* src) {
    const ulonglong2* s = (const ulonglong2*)src;
    #pragma unroll
    for (int j = 0; j < 16; j++) {
        ulonglong2 v = s[j];
        dst[2 * j] = v.x; dst[2 * j + 1] = v.y;
    }
}
__device__ __forceinline__ void load_row16(ull* dst, const float* src) {
    const ulonglong2* s = (const ulonglong2*)src;
    #pragma unroll
    for (int j = 0; j < 8; j++) {
        ulonglong2 v = s[j];
        dst[2 * j] = v.x; dst[2 * j + 1] = v.y;
    }
}

// ---------------------------------------------------------------------------
// Pipe-balanced warp-specialized scan. One block per batch, 128 threads:
//   tid [0,64)  (warps 0,1): gate thread p — full r-row p (32 fma2) +
//       n-row (2H+p) cols 0-31 (16 fma2) = 48 fma2.
//   tid [64,128)(warps 2,3): producer p — full z-row H+p (32 fma2) +
//       n-row (2H+p) cols 32-63 (16 fma2) = 48 fma2.
//   -> 1 warp/SMSP x 48 fma2 x rt4 = 192-cyc balanced FMA floor;
//      zero intra-warp divergence in the hot loop.
// Producer publishes float2{sigma(z-pre), n-half}; gate adds its own n-half
// (bias folded there), tanh, blend.
// Barriers: bar1 (zn ready: producers arrive, gates sync, count 128)
//           bar3 (h ready: full sync by all 128)
// ---------------------------------------------------------------------------
__global__ void __launch_bounds__(BT, 1) gru_scan_kernel(
    const float* __restrict__ x,
    const float* __restrict__ W_ih,
    const float* __restrict__ W_hh,
    const float* __restrict__ b_ih,
    const float* __restrict__ b_hh,
    float* __restrict__ states)
{
    const int b = blockIdx.x;
    const int tid = threadIdx.x;
    const int p = tid & 63;              // h-index owned

    __shared__ float h_sh[HH];
    __shared__ float2 zn_sh[HH];         // .x = sigma(z-pre), .y = n-half (cols 32-63)
    __shared__ float x_sh[2][XCHUNK];

    const float* xb = x + (size_t)b * TT;
    float* st_base = states + (size_t)b * TT * HH;

    if (tid < HH) {
        h_sh[tid] = 0.0f;
        x_sh[0][tid] = xb[tid];
    }
    __syncthreads();

    if (tid < 64) {
        // ------------- gate threads: r-row full + n-row cols 0-31 -------------
        ull wr_[32], wn_[16];
        load_row32(wr_, W_hh + (size_t)p * HH);
        load_row16(wn_, W_hh + (size_t)(2 * HH + p) * HH);
        const float b_r = b_hh[p];
        const float b_n = b_hh[2 * HH + p];
        const float wir = W_ih[p],          bir = b_ih[p];
        const float win = W_ih[2 * HH + p], bin = b_ih[2 * HH + p];

        float h = 0.0f, xnext = 0.0f;
        int tmod = 0, buf = 0;

        for (int t = 0; t < TT; t++) {
            // x double-buffer: LDG at chunk start, commit mid-chunk
            if (tmod == 0) {
                int tn = t + XCHUNK;
                if (tn < TT) xnext = xb[tn + p];
            } else if (tmod == XCHUNK / 2) {
                if (t + XCHUNK / 2 < TT) x_sh[buf ^ 1][p] = xnext;
            }
            const float xt = x_sh[buf][tmod];

            // full h into regs: 16 broadcast LDS.128 -> 32 ull (64 floats)
            ull hv[32];
            load_row32(hv, h_sh);

            // r dot (32 fma2, 4 acc); n-half dot over cols 0-31 (16 fma2, 4 acc)
            ull r0 = pack2(b_r, 0.0f), r1 = 0ull, r2 = 0ull, r3 = 0ull;
            ull n0 = pack2(b_n, 0.0f), n1 = 0ull, n2 = 0ull, n3 = 0ull;
            #pragma unroll
            for (int j = 0; j < 8; j++) {
                r0 = fma2(wr_[4 * j],     hv[4 * j],     r0);
                r1 = fma2(wr_[4 * j + 1], hv[4 * j + 1], r1);
                r2 = fma2(wr_[4 * j + 2], hv[4 * j + 2], r2);
                r3 = fma2(wr_[4 * j + 3], hv[4 * j + 3], r3);
            }
            #pragma unroll
            for (int j = 0; j < 4; j++) {
                n0 = fma2(wn_[4 * j],     hv[4 * j],     n0);
                n1 = fma2(wn_[4 * j + 1], hv[4 * j + 1], n1);
                n2 = fma2(wn_[4 * j + 2], hv[4 * j + 2], n2);
                n3 = fma2(wn_[4 * j + 3], hv[4 * j + 3], n3);
            }
            float rlo, rhi, nlo, nhi;
            unpack2(add2(add2(r0, r1), add2(r2, r3)), rlo, rhi);
            unpack2(add2(add2(n0, n1), add2(n2, n3)), nlo, nhi);
            const float r = sig_a(fmaf(xt, wir, bir) + rlo + rhi);
            const float nhalf = nlo + nhi;
            const float xpn = fmaf(xt, win, bin);

            NBAR_SYNC(1, BT);                    // wait producer publishes
            const float2 zn = zn_sh[p];          // one LDS.64
            const float ghn = nhalf + zn.y;      // full n recurrent dot
            const float n = tanh_a(fmaf(r, ghn, xpn));
            h = n + zn.x * (h - n);              // (1-z)*n + z*h
            h_sh[p] = h;
            st_base[(size_t)t * HH + p] = h;     // coalesced, fire-and-forget
            NBAR_SYNC(3, BT);                    // h visible to all

            if (++tmod == XCHUNK) { tmod = 0; buf ^= 1; }
        }
    } else {
        // ----------- producers: z-row full + n-row cols 32-63 -----------
        ull wz_[32], wn_[16];
        load_row32(wz_, W_hh + (size_t)(HH + p) * HH);
        load_row16(wn_, W_hh + (size_t)(2 * HH + p) * HH + 32);
        const float b_z = b_hh[HH + p];
        const float wiz = W_ih[HH + p], biz = b_ih[HH + p];
        int tmod = 0, buf = 0;

        for (int t = 0; t < TT; t++) {
            ull hv[32];
            load_row32(hv, h_sh);

            ull z0 = pack2(b_z, 0.0f), z1 = 0ull, z2 = 0ull, z3 = 0ull;
            ull n0 = 0ull, n1 = 0ull, n2 = 0ull, n3 = 0ull;
            #pragma unroll
            for (int j = 0; j < 8; j++) {
                z0 = fma2(wz_[4 * j],     hv[4 * j],     z0);
                z1 = fma2(wz_[4 * j + 1], hv[4 * j + 1], z1);
                z2 = fma2(wz_[4 * j + 2], hv[4 * j + 2], z2);
                z3 = fma2(wz_[4 * j + 3], hv[4 * j + 3], z3);
            }
            #pragma unroll
            for (int j = 0; j < 4; j++) {       // cols 32-63 = hv[16..31]
                n0 = fma2(wn_[4 * j],     hv[16 + 4 * j],     n0);
                n1 = fma2(wn_[4 * j + 1], hv[16 + 4 * j + 1], n1);
                n2 = fma2(wn_[4 * j + 2], hv[16 + 4 * j + 2], n2);
                n3 = fma2(wn_[4 * j + 3], hv[16 + 4 * j + 3], n3);
            }
            float zlo, zhi, nlo, nhi;
            unpack2(add2(add2(z0, z1), add2(z2, z3)), zlo, zhi);
            unpack2(add2(add2(n0, n1), add2(n2, n3)), nlo, nhi);
            const float xt = x_sh[buf][tmod];    // broadcast LDS
            float2 o;
            o.x = sig_a(fmaf(xt, wiz, biz) + zlo + zhi);
            o.y = nlo + nhi;
            zn_sh[p] = o;                        // one STS.64
            NBAR_ARRIVE(1, BT);
            NBAR_SYNC(3, BT);
            if (++tmod == XCHUNK) { tmod = 0; buf ^= 1; }
        }
    }
}

// ---------------------------------------------------------------------------
// Head: out[b,t] = states[b,t,:].W_out + b_out + x[b,t]. One warp per (b,t).
// ---------------------------------------------------------------------------
__global__ void head_kernel(const float* __restrict__ states,
                            const float* __restrict__ x,
                            const float* __restrict__ W_out,
                            const float* __restrict__ b_out,
                            float* __restrict__ out)
{
    const int lane = threadIdx.x & 31;
    const int warp = (int)((blockIdx.x * blockDim.x + threadIdx.x) >> 5);
    const int nw = (int)((gridDim.x * blockDim.x) >> 5);
    const float w0 = W_out[lane];
    const float w1 = W_out[32 + lane];
    const float bo = b_out[0];
    const long total = (long)NB * TT;
    for (long i = warp; i < total; i += nw) {
        const float* s = states + (size_t)i * HH;
        float p = fmaf(s[lane], w0, s[lane + 32] * w1);
        #pragma unroll
        for (int o = 16; o > 0; o >>= 1)
            p += __shfl_xor_sync(0xffffffffu, p, o);
        if (lane == 0) out[i] = p + bo + x[i];
    }
}

extern "C" void kernel_launch(void* const* d_in, const int* in_sizes, int n_in,
                              void* d_out, int out_size) {
    const float* x     = (const float*)d_in[0];
    const float* W_ih  = (const float*)d_in[1];
    const float* W_hh  = (const float*)d_in[2];
    const float* b_ih  = (const float*)d_in[3];
    const float* b_hh  = (const float*)d_in[4];
    const float* W_out = (const float*)d_in[5];
    const float* b_out = (const float*)d_in[6];

    float* out    = (float*)d_out;              // [B*T]   (tuple elem 0)
    float* states = out + (size_t)NB * TT;      // [B*T*H] (tuple elem 1)

    gru_scan_kernel<<<NB, BT>>>(x, W_ih, W_hh, b_ih, b_hh, states);
    head_kernel<<<512, 256>>>(states, x, W_out, b_out, out);
}

// round 17
// speedup vs baseline: 3.1862x; 1.0004x over previous
#include <cuda_runtime.h>
#include <cuda_fp16.h>

#define NB 32
#define TT 16384
#define HH 64
#define BT 128         // 4 warps: 2 gate, 2 producer
#define XCHUNK 64      // x prefetch chunk

typedef unsigned long long ull;

// ---- packed f32x2 helpers ----
__device__ __forceinline__ ull fma2(ull a, ull b, ull c) {
    ull d;
    asm("fma.rn.f32x2 %0, %1, %2, %3;" : "=l"(d) : "l"(a), "l"(b), "l"(c));
    return d;
}
__device__ __forceinline__ ull add2(ull a, ull b) {
    ull d;
    asm("add.rn.f32x2 %0, %1, %2;" : "=l"(d) : "l"(a), "l"(b));
    return d;
}
__device__ __forceinline__ void unpack2(ull v, float& lo, float& hi) {
    asm("mov.b64 {%0, %1}, %2;" : "=f"(lo), "=f"(hi) : "l"(v));
}
__device__ __forceinline__ ull pack2(float lo, float hi) {
    ull v;
    asm("mov.b64 %0, {%1, %2};" : "=l"(v) : "f"(lo), "f"(hi));
    return v;
}

// MUFU.TANH gates — validated rel_err ~2e-6 over the full recurrence
__device__ __forceinline__ float tanh_a(float v) {
    float r;
    asm("tanh.approx.f32 %0, %1;" : "=f"(r) : "f"(v));
    return r;
}
__device__ __forceinline__ float sig_a(float v) {
    return fmaf(0.5f, tanh_a(0.5f * v), 0.5f);
}

#define NBAR_SYNC(id, cnt) \
    asm volatile("bar.sync %0, %1;" :: "r"(id), "r"(cnt) : "memory")
#define NBAR_ARRIVE(id, cnt) \
    asm volatile("bar.arrive %0, %1;" :: "r"(id), "r"(cnt) : "memory")

// load 32 floats (16 ull) via 16B vectors
__device__ __forceinline__ void load_row16(ull* dst, const float* src) {
    const ulonglong2* s = (const ulonglong2*)src;
    #pragma unroll
    for (int j = 0; j < 8; j++) {
        ulonglong2 v = s[j];
        dst[2 * j] = v.x; dst[2 * j + 1] = v.y;
    }
}

// fp16 64-wide dot: 32 HFMA2 (rt2 -> 64 cyc pipe), 4 half2 accumulators,
// combined in fp32. w16: 32 half2 register-resident weights.
__device__ __forceinline__ float dot64_h2(const __half2* w16,
                                          const __half* h16_sh) {
    __half2 hv[32];
    {
        const uint4* hp = (const uint4*)h16_sh;   // 128B = 8 x 16B
        #pragma unroll
        for (int j = 0; j < 8; j++) {
            uint4 v = hp[j];
            hv[4 * j]     = *reinterpret_cast<__half2*>(&v.x);
            hv[4 * j + 1] = *reinterpret_cast<__half2*>(&v.y);
            hv[4 * j + 2] = *reinterpret_cast<__half2*>(&v.z);
            hv[4 * j + 3] = *reinterpret_cast<__half2*>(&v.w);
        }
    }
    __half2 a0 = __float2half2_rn(0.0f), a1 = a0, a2 = a0, a3 = a0;
    #pragma unroll
    for (int j = 0; j < 8; j++) {
        a0 = __hfma2(w16[4 * j],     hv[4 * j],     a0);
        a1 = __hfma2(w16[4 * j + 1], hv[4 * j + 1], a1);
        a2 = __hfma2(w16[4 * j + 2], hv[4 * j + 2], a2);
        a3 = __hfma2(w16[4 * j + 3], hv[4 * j + 3], a3);
    }
    const float2 f0 = __half22float2(__hadd2(a0, a1));
    const float2 f1 = __half22float2(__hadd2(a2, a3));
    return (f0.x + f0.y) + (f1.x + f1.y);
}

// ---------------------------------------------------------------------------
// Mixed-precision pipe-balanced scan. One block per batch, 128 threads:
//   tid [0,64)  (warps 0,1): gate p — r-row in fp16 (32 HFMA2, 64 cyc) +
//       n-row cols 0-31 in fp32 (16 fma2, 64 cyc) = 128-cyc pipe.
//   tid [64,128)(warps 2,3): producer p — z-row fp16 + n-row cols 32-63 fp32.
//   n stays fp32 (its error enters h directly); r/z fp16 errors are
//   attenuated by sigmoid (L=1/4) and small multipliers.
// Producer publishes float2{sigma(z-pre), n-half}; gate finishes tail.
// Barriers: bar1 (zn ready), bar3 (h ready) — identical to R15.
// ---------------------------------------------------------------------------
__global__ void __launch_bounds__(BT, 1) gru_scan_kernel(
    const float* __restrict__ x,
    const float* __restrict__ W_ih,
    const float* __restrict__ W_hh,
    const float* __restrict__ b_ih,
    const float* __restrict__ b_hh,
    float* __restrict__ states)
{
    const int b = blockIdx.x;
    const int tid = threadIdx.x;
    const int p = tid & 63;              // h-index owned

    __shared__ float  h_sh[HH];          // fp32 h (n-dots)
    __shared__ __half h16_sh[HH];        // fp16 h (r/z dots)
    __shared__ float2 zn_sh[HH];         // .x = sigma(z-pre), .y = n-half
    __shared__ float  x_sh[2][XCHUNK];

    const float* xb = x + (size_t)b * TT;
    float* st_base = states + (size_t)b * TT * HH;

    if (tid < HH) {
        h_sh[tid] = 0.0f;
        h16_sh[tid] = __float2half_rn(0.0f);
        x_sh[0][tid] = xb[tid];
    }
    __syncthreads();

    if (tid < 64) {
        // ---------- gate threads: r-row (fp16) + n-row cols 0-31 (fp32) ----------
        __half2 wr16[32];
        {
            const float* rowr = W_hh + (size_t)p * HH;
            #pragma unroll
            for (int j = 0; j < 32; j++)
                wr16[j] = __floats2half2_rn(rowr[2 * j], rowr[2 * j + 1]);
        }
        ull wn_[16];
        load_row16(wn_, W_hh + (size_t)(2 * HH + p) * HH);
        const float b_r = b_hh[p];
        const float b_n = b_hh[2 * HH + p];
        const float wir = W_ih[p],          bir = b_ih[p];
        const float win = W_ih[2 * HH + p], bin = b_ih[2 * HH + p];

        float h = 0.0f, xnext = 0.0f;
        int tmod = 0, buf = 0;

        for (int t = 0; t < TT; t++) {
            // x double-buffer: LDG at chunk start, commit mid-chunk
            if (tmod == 0) {
                int tn = t + XCHUNK;
                if (tn < TT) xnext = xb[tn + p];
            } else if (tmod == XCHUNK / 2) {
                if (t + XCHUNK / 2 < TT) x_sh[buf ^ 1][p] = xnext;
            }
            const float xt = x_sh[buf][tmod];

            // r dot in fp16 (64 cyc pipe)
            const float rdot = dot64_h2(wr16, h16_sh);

            // n-half dot cols 0-31 in fp32 (16 fma2, 64 cyc pipe)
            ull hv[16];
            load_row16(hv, h_sh);
            ull n0 = pack2(b_n, 0.0f), n1 = 0ull, n2 = 0ull, n3 = 0ull;
            #pragma unroll
            for (int j = 0; j < 4; j++) {
                n0 = fma2(wn_[4 * j],     hv[4 * j],     n0);
                n1 = fma2(wn_[4 * j + 1], hv[4 * j + 1], n1);
                n2 = fma2(wn_[4 * j + 2], hv[4 * j + 2], n2);
                n3 = fma2(wn_[4 * j + 3], hv[4 * j + 3], n3);
            }
            float nlo, nhi;
            unpack2(add2(add2(n0, n1), add2(n2, n3)), nlo, nhi);

            const float r = sig_a(fmaf(xt, wir, bir) + rdot + b_r);
            const float nhalf = nlo + nhi;
            const float xpn = fmaf(xt, win, bin);

            NBAR_SYNC(1, BT);                    // wait producer publishes
            const float2 zn = zn_sh[p];          // one LDS.64
            const float ghn = nhalf + zn.y;      // full n recurrent dot
            const float n = tanh_a(fmaf(r, ghn, xpn));
            h = n + zn.x * (h - n);              // (1-z)*n + z*h
            h_sh[p] = h;
            h16_sh[p] = __float2half_rn(h);
            st_base[(size_t)t * HH + p] = h;     // coalesced, fire-and-forget
            NBAR_SYNC(3, BT);                    // h visible to all

            if (++tmod == XCHUNK) { tmod = 0; buf ^= 1; }
        }
    } else {
        // -------- producers: z-row (fp16) + n-row cols 32-63 (fp32) --------
        __half2 wz16[32];
        {
            const float* rowz = W_hh + (size_t)(HH + p) * HH;
            #pragma unroll
            for (int j = 0; j < 32; j++)
                wz16[j] = __floats2half2_rn(rowz[2 * j], rowz[2 * j + 1]);
        }
        ull wn_[16];
        load_row16(wn_, W_hh + (size_t)(2 * HH + p) * HH + 32);
        const float b_z = b_hh[HH + p];
        const float wiz = W_ih[HH + p], biz = b_ih[HH + p];
        int tmod = 0, buf = 0;

        for (int t = 0; t < TT; t++) {
            const float zdot = dot64_h2(wz16, h16_sh);

            ull hv[16];
            load_row16(hv, h_sh + 32);           // cols 32-63
            ull n0 = 0ull, n1 = 0ull, n2 = 0ull, n3 = 0ull;
            #pragma unroll
            for (int j = 0; j < 4; j++) {
                n0 = fma2(wn_[4 * j],     hv[4 * j],     n0);
                n1 = fma2(wn_[4 * j + 1], hv[4 * j + 1], n1);
                n2 = fma2(wn_[4 * j + 2], hv[4 * j + 2], n2);
                n3 = fma2(wn_[4 * j + 3], hv[4 * j + 3], n3);
            }
            float nlo, nhi;
            unpack2(add2(add2(n0, n1), add2(n2, n3)), nlo, nhi);

            const float xt = x_sh[buf][tmod];    // broadcast LDS
            float2 o;
            o.x = sig_a(fmaf(xt, wiz, biz) + zdot + b_z);
            o.y = nlo + nhi;
            zn_sh[p] = o;                        // one STS.64
            NBAR_ARRIVE(1, BT);
            NBAR_SYNC(3, BT);
            if (++tmod == XCHUNK) { tmod = 0; buf ^= 1; }
        }
    }
}

// ---------------------------------------------------------------------------
// Head: out[b,t] = states[b,t,:].W_out + b_out + x[b,t]. One warp per (b,t).
// ---------------------------------------------------------------------------
__global__ void head_kernel(const float* __restrict__ states,
                            const float* __restrict__ x,
                            const float* __restrict__ W_out,
                            const float* __restrict__ b_out,
                            float* __restrict__ out)
{
    const int lane = threadIdx.x & 31;
    const int warp = (int)((blockIdx.x * blockDim.x + threadIdx.x) >> 5);
    const int nw = (int)((gridDim.x * blockDim.x) >> 5);
    const float w0 = W_out[lane];
    const float w1 = W_out[32 + lane];
    const float bo = b_out[0];
    const long total = (long)NB * TT;
    for (long i = warp; i < total; i += nw) {
        const float* s = states + (size_t)i * HH;
        float p = fmaf(s[lane], w0, s[lane + 32] * w1);
        #pragma unroll
        for (int o = 16; o > 0; o >>= 1)
            p += __shfl_xor_sync(0xffffffffu, p, o);
        if (lane == 0) out[i] = p + bo + x[i];
    }
}

extern "C" void kernel_launch(void* const* d_in, const int* in_sizes, int n_in,
                              void* d_out, int out_size) {
    const float* x     = (const float*)d_in[0];
    const float* W_ih  = (const float*)d_in[1];
    const float* W_hh  = (const float*)d_in[2];
    const float* b_ih  = (const float*)d_in[3];
    const float* b_hh  = (const float*)d_in[4];
    const float* W_out = (const float*)d_in[5];
    const float* b_out = (const float*)d_in[6];

    float* out    = (float*)d_out;              // [B*T]   (tuple elem 0)
    float* states = out + (size_t)NB * TT;      // [B*T*H] (tuple elem 1)

    gru_scan_kernel<<<NB, BT>>>(x, W_ih, W_hh, b_ih, b_hh, states);
    head_kernel<<<512, 256>>>(states, x, W_out, b_out, out);
}